// round 16
// baseline (speedup 1.0000x reference)
#include <cuda_runtime.h>
#include <cuda_bf16.h>

// Problem constants (fixed by the reference setup_inputs)
#define BB 64
#define SS 512
#define HH 768
#define WW 256      // MAX_WORD_LEN
#define WE 300
#define OUTW (HH + WE)   // 1068 floats
#define HV  (HH/4)       // 192 float4
#define WV  (WE/4)       // 75 float4

// One CTA per (batch, word), 128 threads, 16384 CTAs. NO smem, NO barriers:
// each warp independently loads all 512 sorted token_ids (4 coalesced int4
// per thread), counts lo = #ids<w and cnt = #ids==w over its 16 ids, and a
// single warp redux broadcasts the totals. Token reads are L2-hits (128 KB
// working set) — trades spare L2 bandwidth for removing the CTA-wide
// __syncthreads from the critical path, so warps run fully decoupled.
// Reduction = depth-4 predicated prefetch (MLP~8/warp), streaming hints.
__global__ __launch_bounds__(128)
void embeddings_fused_kernel(const float* __restrict__ hidden,
                             const float* __restrict__ w2v,
                             const int*   __restrict__ token_ids,
                             const int*   __restrict__ word_ids,
                             float*       __restrict__ out)
{
    const int bw   = blockIdx.x;        // 0 .. B*W-1
    const int b    = bw >> 8;
    const int w    = bw & (WW - 1);
    const int tid  = threadIdx.x;
    const int lane = tid & 31;

    // ---- start the independent w2v gather early (overlaps the count) ----
    const int wid = __ldg(&word_ids[bw]);
    const bool hasw = (tid < WV);
    float4 gv;
    if (hasw) {
        gv = __ldg(reinterpret_cast<const float4*>(w2v + (size_t)wid * WE) + tid);
    }

    // ---- warp-private parallel count: 4 int4 per thread = all 512 ids ----
    const int4* tb = reinterpret_cast<const int4*>(token_ids + b * SS);
    const int4 v0 = __ldg(tb + lane);
    const int4 v1 = __ldg(tb + lane + 32);
    const int4 v2 = __ldg(tb + lane + 64);
    const int4 v3 = __ldg(tb + lane + 96);
    int c = (v0.x <  w) + (v0.y <  w) + (v0.z <  w) + (v0.w <  w)
          + (v1.x <  w) + (v1.y <  w) + (v1.z <  w) + (v1.w <  w)
          + (v2.x <  w) + (v2.y <  w) + (v2.z <  w) + (v2.w <  w)
          + (v3.x <  w) + (v3.y <  w) + (v3.z <  w) + (v3.w <  w);
    int d = (v0.x == w) + (v0.y == w) + (v0.z == w) + (v0.w == w)
          + (v1.x == w) + (v1.y == w) + (v1.z == w) + (v1.w == w)
          + (v2.x == w) + (v2.y == w) + (v2.z == w) + (v2.w == w)
          + (v3.x == w) + (v3.y == w) + (v3.z == w) + (v3.w == w);
    const int sum = __reduce_add_sync(0xffffffffu, c | (d << 16));
    const int lo  = sum & 0xffff;
    const int cnt = sum >> 16;
    const float inv = (cnt > 0) ? (1.0f / (float)cnt) : 0.0f;

    float4* orow = reinterpret_cast<float4*>(out + (size_t)bw * OUTW);

    const float4* rbase = reinterpret_cast<const float4*>(hidden + (size_t)b * SS * HH)
                          + (size_t)lo * HV;
    const bool has2 = (tid < (HV - 128));   // tid < 64
    const float4 z = make_float4(0.f, 0.f, 0.f, 0.f);

    // ---- depth-4 predicated prefetch, both chains, before any FADD ----
    const float4* c0 = rbase + tid;
    const float4* c1 = rbase + tid + 128;
    float4 t0 = (cnt > 0) ? __ldcs(c0 + 0 * HV) : z;
    float4 t1 = (cnt > 1) ? __ldcs(c0 + 1 * HV) : z;
    float4 t2 = (cnt > 2) ? __ldcs(c0 + 2 * HV) : z;
    float4 t3 = (cnt > 3) ? __ldcs(c0 + 3 * HV) : z;
    float4 u0 = (has2 && cnt > 0) ? __ldcs(c1 + 0 * HV) : z;
    float4 u1 = (has2 && cnt > 1) ? __ldcs(c1 + 1 * HV) : z;
    float4 u2 = (has2 && cnt > 2) ? __ldcs(c1 + 2 * HV) : z;
    float4 u3 = (has2 && cnt > 3) ? __ldcs(c1 + 3 * HV) : z;

    float4 a0, a1;
    a0.x = (t0.x + t1.x) + (t2.x + t3.x);
    a0.y = (t0.y + t1.y) + (t2.y + t3.y);
    a0.z = (t0.z + t1.z) + (t2.z + t3.z);
    a0.w = (t0.w + t1.w) + (t2.w + t3.w);
    a1.x = (u0.x + u1.x) + (u2.x + u3.x);
    a1.y = (u0.y + u1.y) + (u2.y + u3.y);
    a1.z = (u0.z + u1.z) + (u2.z + u3.z);
    a1.w = (u0.w + u1.w) + (u2.w + u3.w);

    // ---- rare remainder (cnt > 4) ----
    #pragma unroll 1
    for (int s = 4; s < cnt; ++s) {
        float4 p0 = __ldcs(c0 + (size_t)s * HV);
        a0.x += p0.x; a0.y += p0.y; a0.z += p0.z; a0.w += p0.w;
        if (has2) {
            float4 p1 = __ldcs(c1 + (size_t)s * HV);
            a1.x += p1.x; a1.y += p1.y; a1.z += p1.z; a1.w += p1.w;
        }
    }

    a0.x *= inv; a0.y *= inv; a0.z *= inv; a0.w *= inv;
    __stcs(&orow[tid], a0);
    if (has2) {
        a1.x *= inv; a1.y *= inv; a1.z *= inv; a1.w *= inv;
        __stcs(&orow[tid + 128], a1);
    }
    if (hasw) {
        __stcs(&orow[HV + tid], gv);
    }
}

extern "C" void kernel_launch(void* const* d_in, const int* in_sizes, int n_in,
                              void* d_out, int out_size)
{
    // Identify inputs by element count (robust to ordering):
    //   hidden    : 64*512*768  = 25,165,824 (float32)
    //   w2v_table : 50000*300   = 15,000,000 (float32)
    //   token_ids : 64*512      = 32,768     (int32)
    //   word_ids  : 64*256      = 16,384     (int32)
    const float* hidden = nullptr;
    const float* w2v    = nullptr;
    const int*   tok    = nullptr;
    const int*   wids   = nullptr;
    for (int i = 0; i < n_in; ++i) {
        switch (in_sizes[i]) {
            case 25165824: hidden = (const float*)d_in[i]; break;
            case 15000000: w2v    = (const float*)d_in[i]; break;
            case 32768:    tok    = (const int*)d_in[i];   break;
            case 16384:    wids   = (const int*)d_in[i];   break;
            default: break;
        }
    }
    float* out = (float*)d_out;

    embeddings_fused_kernel<<<BB * WW, 128>>>(hidden, w2v, tok, wids, out);
}